// round 8
// baseline (speedup 1.0000x reference)
#include <cuda_runtime.h>

#define BATCH   2
#define SEQ     1024
#define HEADS   8
#define DEP     64
#define NF      64
#define BH      (BATCH*HEADS)   // 16
#define DMODEL  512
#define CHUNK   64
#define NCH     (SEQ/CHUNK)     // 16

typedef unsigned long long u64;

// ---------------- scratch (static device globals; no allocation) ----------------
__device__ float g_Mqt[DEP*NF];              // Mq transposed: [d][f]
__device__ float g_Mkt[DEP*NF];              // Mk transposed: [d][f]
__device__ float g_Wvt[DEP*DEP];             // Wv transposed: [d][e]
__device__ float g_Wfct[DMODEL*DMODEL];      // Wfc transposed: [e][o]
__device__ float g_cbq[NF];
__device__ float g_cbk[NF];
__device__ float g_pS[BH*NCH*NF*DEP];        // per-chunk sum of kf ⊗ vp
__device__ float g_pK[BH*NCH*NF];            // per-chunk sum of kf
__device__ float g_attn[BATCH*SEQ*DMODEL];   // attention out, [b][s][h*64+d]
__device__ unsigned g_done[BH];              // per-bh chunk-completion bitmask (pS/pK)
__device__ unsigned g_adone[BATCH*NCH];      // per-(b,c) attn-row completion counter (8 heads)

// ---------------- packed f32x2 helpers (sm_103a FFMA2) ----------------
__device__ __forceinline__ u64 pk2(float x) {
    u64 r; asm("mov.b64 %0, {%1,%1};" : "=l"(r) : "f"(x)); return r;
}
__device__ __forceinline__ u64 pk2b(float x, float y) {
    u64 r; asm("mov.b64 %0, {%1,%2};" : "=l"(r) : "f"(x), "f"(y)); return r;
}
__device__ __forceinline__ void fma2(u64& d, u64 a, u64 b) {
    asm("fma.rn.f32x2 %0, %1, %2, %0;" : "+l"(d) : "l"(a), "l"(b));
}
__device__ __forceinline__ float2 upk(u64 v) {
    float2 f; asm("mov.b64 {%0,%1}, %2;" : "=f"(f.x), "=f"(f.y) : "l"(v)); return f;
}

// ---------------- 4x4 micro-kernel (prep) ----------------
template<int LDA, int LDB>
__device__ __forceinline__ void micro4p(const float* As, const float* Bs,
                                        int rb, int cb, int k, u64 acc[4][2]) {
    float a[4][4];
#pragma unroll
    for (int i = 0; i < 4; i++)
        *(float4*)a[i] = *(const float4*)&As[(rb + i) * LDA + k];
    u64 b[4][2];
#pragma unroll
    for (int kk = 0; kk < 4; kk++)
        *(ulonglong2*)b[kk] = *(const ulonglong2*)&Bs[(k + kk) * LDB + cb];
#pragma unroll
    for (int kk = 0; kk < 4; kk++)
#pragma unroll
        for (int i = 0; i < 4; i++) {
            u64 ad = pk2(a[i][kk]);
            fma2(acc[i][0], ad, b[kk][0]);
            fma2(acc[i][1], ad, b[kk][1]);
        }
}

// ---------------- 8x4 micro-kernel (mega GEMMs) ----------------
template<int LDA, int LDB>
__device__ __forceinline__ void micro84p(const float* As, const float* Bs,
                                         int rb, int cb, int k, u64 acc[8][2]) {
    float a[8][4];
#pragma unroll
    for (int i = 0; i < 8; i++)
        *(float4*)a[i] = *(const float4*)&As[(rb + i) * LDA + k];
#pragma unroll
    for (int kk = 0; kk < 4; kk++) {
        u64 b[2];
        *(ulonglong2*)b = *(const ulonglong2*)&Bs[(k + kk) * LDB + cb];
#pragma unroll
        for (int i = 0; i < 8; i++) {
            u64 ad = pk2(a[i][kk]);
            fma2(acc[i][0], ad, b[0]);
            fma2(acc[i][1], ad, b[1]);
        }
    }
}

// ---------------- 8x8 split-column micro-kernel (fc): cols cb..cb+3 and cb+64..cb+67 ----------------
// Split columns keep the B-operand LDS.128 phases bank-conflict-free.
template<int LDA, int LDB>
__device__ __forceinline__ void micro88s(const float* As, const float* Bs,
                                         int rb, int cb, int k, u64 acc[8][4]) {
    float a[8][4];
#pragma unroll
    for (int i = 0; i < 8; i++)
        *(float4*)a[i] = *(const float4*)&As[(rb + i) * LDA + k];
#pragma unroll
    for (int kk = 0; kk < 4; kk++) {
        u64 b[4];
        *(ulonglong2*)&b[0] = *(const ulonglong2*)&Bs[(k + kk) * LDB + cb];
        *(ulonglong2*)&b[2] = *(const ulonglong2*)&Bs[(k + kk) * LDB + cb + 64];
#pragma unroll
        for (int i = 0; i < 8; i++) {
            u64 ad = pk2(a[i][kk]);
            fma2(acc[i][0], ad, b[0]);
            fma2(acc[i][1], ad, b[1]);
            fma2(acc[i][2], ad, b[2]);
            fma2(acc[i][3], ad, b[3]);
        }
    }
}

// ---------------- K0: fold Linear+ORF (transposed), transpose Wv & Wfc, reset flags ----------------
__global__ void prep_kernel(const float* __restrict__ Wq, const float* __restrict__ bq,
                            const float* __restrict__ Wk, const float* __restrict__ bk,
                            const float* __restrict__ orfq, const float* __restrict__ orfk,
                            const float* __restrict__ Wv, const float* __restrict__ Wfc) {
    int tid = threadIdx.x;
    if (blockIdx.x >= 3) {   // blocks 3..10: Wfc^T (g_Wfct[e][o] = Wfc[o][e])
        int t = (blockIdx.x - 3) * 256 + tid;   // 0..2047
#pragma unroll 4
        for (int j = 0; j < 32; j++) {
            int idx4 = t * 32 + j;              // float4 index into g_Wfct
            int e = idx4 >> 7;
            int o4 = (idx4 & 127) * 4;
            float4 w;
            w.x = Wfc[(size_t)(o4 + 0) * DMODEL + e];
            w.y = Wfc[(size_t)(o4 + 1) * DMODEL + e];
            w.z = Wfc[(size_t)(o4 + 2) * DMODEL + e];
            w.w = Wfc[(size_t)(o4 + 3) * DMODEL + e];
            *(float4*)&g_Wfct[(size_t)e * DMODEL + o4] = w;
        }
        return;
    }
    if (blockIdx.x == 2) {   // Wv^T
        for (int i = tid; i < 4096; i += 256) {
            int e = i >> 6, d = i & 63;
            g_Wvt[d * 64 + e] = Wv[i];
        }
        return;
    }
    __shared__ float orf_s[4096];   // [f][e]
    __shared__ float W_s[4096];     // [e][d]
    __shared__ float b_s[64];
    const float norm = 0.35355339059327379f;  // 64^(-0.25)
    int s = blockIdx.x;
    const float* orf = s ? orfk : orfq;
    const float* W   = s ? Wk   : Wq;
    const float* bb  = s ? bk   : bq;
    float* Mt = s ? g_Mkt : g_Mqt;
    float* cb = s ? g_cbk : g_cbq;
    if (s == 0) {   // reset completion flags each launch (graph-replay determinism)
        if (tid < BH) g_done[tid] = 0u;
        if (tid < BATCH * NCH) g_adone[tid] = 0u;
    }
    for (int i = tid; i < 1024; i += 256) {
        ((float4*)orf_s)[i] = ((const float4*)orf)[i];
        ((float4*)W_s)[i]   = ((const float4*)W)[i];
    }
    if (tid < 64) b_s[tid] = bb[tid];
    __syncthreads();

    int rt = tid >> 4, ct = tid & 15;
    u64 acc[4][2] = {};
#pragma unroll
    for (int k = 0; k < 64; k += 4)
        micro4p<64, 64>(orf_s, W_s, 4 * rt, 4 * ct, k, acc);
#pragma unroll
    for (int i = 0; i < 4; i++) {
        float2 p0 = upk(acc[i][0]), p1 = upk(acc[i][1]);
        float vals[4] = { p0.x, p0.y, p1.x, p1.y };
#pragma unroll
        for (int j = 0; j < 4; j++)          // transposed store: Mt[d][f]
            Mt[(4 * ct + j) * 64 + (4 * rt + i)] = norm * vals[j];
    }
    if (tid < 64) {
        float a = 0.f;
#pragma unroll
        for (int e = 0; e < 64; e++) a += orf_s[tid * 64 + e] * b_s[e];
        cb[tid] = norm * a;
    }
}

// ---------------- K1 (combined): mega attention blocks + overlapped fc blocks ----------------
// bids 0..255: mega (bh = bid&15, c = bid>>4). bids 256..383: fc tiles.
// 80KB smem -> 2 blocks/SM -> 296 wave-1 slots >= 256: all mega blocks wave-1 resident,
// so fc spins always resolve (no deadlock).
__global__ void __launch_bounds__(128) mega_fc_kernel(const float* __restrict__ qin,
                                                      const float* __restrict__ kin,
                                                      const float* __restrict__ vin,
                                                      const float* __restrict__ bv,
                                                      const float* __restrict__ bfc,
                                                      float* __restrict__ out) {
    extern __shared__ float sm[];
    int bid = blockIdx.x, tid = threadIdx.x;

    if (bid >= 256) {
        // ================= fc path: out = attn @ Wfc^T + bfc =================
        float* A_s  = sm;          // 64 x 64
        float* Bt_s = sm + 4096;   // 64 x 128
        int fid = bid - 256;             // 0..127
        int rtile = fid >> 2;            // 0..31  (= b*16 + c)
        int ot = fid & 3;
        int r0 = rtile * 64, o0 = ot * 128;
        int bb_ = rtile >> 4, cc_ = rtile & 15;
        // wait until all 8 heads have written these 64 attn rows
        if (tid == 0) {
            while (atomicAdd(&g_adone[bb_ * NCH + cc_], 0u) < (unsigned)HEADS)
                __nanosleep(256);
        }
        __syncthreads();

        int rt = tid >> 4, ct = tid & 15;   // 8 row-groups x 16 col-groups
        u64 acc[8][4] = {};
        for (int e0 = 0; e0 < DMODEL; e0 += 64) {
            for (int i = tid; i < 1024; i += 128) {
                int r = i >> 4, e4 = (i & 15) * 4;
                float4 v = __ldcg((const float4*)&g_attn[(size_t)(r0 + r) * DMODEL + e0 + e4]);
                *(float4*)&A_s[r * 64 + e4] = v;
            }
            for (int i = tid; i < 2048; i += 128) {
                int e = i >> 5, o4 = (i & 31) * 4;
                *(float4*)&Bt_s[e * 128 + o4] =
                    *(const float4*)&g_Wfct[(size_t)(e0 + e) * DMODEL + o0 + o4];
            }
            __syncthreads();
#pragma unroll
            for (int k = 0; k < 64; k += 4)
                micro88s<64, 128>(A_s, Bt_s, 8 * rt, 4 * ct, k, acc);
            __syncthreads();
        }
        float4 bias0 = *(const float4*)&bfc[o0 + 4 * ct];
        float4 bias1 = *(const float4*)&bfc[o0 + 64 + 4 * ct];
#pragma unroll
        for (int i = 0; i < 8; i++) {
            int r = r0 + 8 * rt + i;
            float2 p0 = upk(acc[i][0]), p1 = upk(acc[i][1]);
            float2 p2 = upk(acc[i][2]), p3 = upk(acc[i][3]);
            *(float4*)&out[(size_t)r * DMODEL + o0 + 4 * ct] =
                make_float4(p0.x + bias0.x, p0.y + bias0.y, p1.x + bias0.z, p1.y + bias0.w);
            *(float4*)&out[(size_t)r * DMODEL + o0 + 64 + 4 * ct] =
                make_float4(p2.x + bias1.x, p2.y + bias1.y, p3.x + bias1.z, p3.y + bias1.w);
        }
        return;
    }

    // ================= mega path =================
    float* X_s  = sm;
    float* w_s  = sm + 4096;
    float* qt_s = sm + 8192;
    float* kf_s = sm + 12288;
    float* vp_s = sm + 16384;
    __shared__ float part_s[128];

    int bh = bid & 15, c = bid >> 4;
    int b = bh >> 3, h = bh & 7;
    int rt = tid >> 4, ct = tid & 15;

    // ---- P0: feature GEMMs for this chunk (q, k, v) ----
#pragma unroll 1
    for (int str = 0; str < 3; str++) {
        const float* inp  = (str == 0) ? qin   : (str == 1) ? kin   : vin;
        const float* wt   = (str == 0) ? g_Mqt : (str == 1) ? g_Mkt : g_Wvt;
        const float* bias = (str == 0) ? g_cbq : (str == 1) ? g_cbk : bv;
        float* dst        = (str == 0) ? qt_s  : (str == 1) ? kf_s  : vp_s;
        const float4* ing = (const float4*)(inp + ((size_t)(b * SEQ + c * CHUNK)) * DMODEL + h * DEP);
        for (int i = tid; i < 1024; i += 128)
            ((float4*)X_s)[i] = ing[(i >> 4) * 128 + (i & 15)];   // [t][d]
        for (int i = tid; i < 1024; i += 128)
            ((float4*)w_s)[i] = ((const float4*)wt)[i];           // [d][out]
        __syncthreads();
        u64 acc[8][2];
        {
            u64 b0 = pk2b(bias[4 * ct + 0], bias[4 * ct + 1]);
            u64 b1 = pk2b(bias[4 * ct + 2], bias[4 * ct + 3]);
#pragma unroll
            for (int i = 0; i < 8; i++) { acc[i][0] = b0; acc[i][1] = b1; }
        }
#pragma unroll
        for (int k = 0; k < 64; k += 4)
            micro84p<64, 64>(X_s, w_s, 8 * rt, 4 * ct, k, acc);
#pragma unroll
        for (int i = 0; i < 8; i++) {
            int row = 8 * rt + i;
            float2 p0 = upk(acc[i][0]), p1 = upk(acc[i][1]);
            float4 vv = make_float4(p0.x, p0.y, p1.x, p1.y);
            if (str < 2) {
                vv.x = fmaxf(vv.x, 0.f) + 0.001f;
                vv.y = fmaxf(vv.y, 0.f) + 0.001f;
                vv.z = fmaxf(vv.z, 0.f) + 0.001f;
                vv.w = fmaxf(vv.w, 0.f) + 0.001f;
            }
            *(float4*)&dst[row * 64 + 4 * ct] = vv;
        }
        __syncthreads();
    }

    // ---- P1: kf^T into X_s, pK partials, pS GEMM; publish ----
    {
        int u = tid >> 1, fb = (tid & 1) * 32;
#pragma unroll
        for (int j = 0; j < 32; j += 4) {
            float4 w = *(const float4*)&kf_s[u * 64 + fb + j];
            X_s[(fb + j + 0) * 64 + u] = w.x;
            X_s[(fb + j + 1) * 64 + u] = w.y;
            X_s[(fb + j + 2) * 64 + u] = w.z;
            X_s[(fb + j + 3) * 64 + u] = w.w;
        }
    }
    {
        int f = tid & 63, hlf = tid >> 6;
        float ps = 0.f;
        for (int u = hlf * 32; u < hlf * 32 + 32; u++) ps += kf_s[u * 64 + f];
        part_s[hlf * 64 + f] = ps;
    }
    __syncthreads();
    {
        u64 acc2[8][2] = {};
#pragma unroll
        for (int k = 0; k < 64; k += 4)
            micro84p<64, 64>(X_s, vp_s, 8 * rt, 4 * ct, k, acc2);
        float* pS_out = g_pS + ((size_t)bh * NCH + c) * 4096;
#pragma unroll
        for (int i = 0; i < 8; i++) {
            float2 p0 = upk(acc2[i][0]), p1 = upk(acc2[i][1]);
            *(float4*)&pS_out[(8 * rt + i) * 64 + 4 * ct] = make_float4(p0.x, p0.y, p1.x, p1.y);
        }
        if (tid < 64)
            g_pK[((size_t)bh * NCH + c) * 64 + tid] = part_s[tid] + part_s[64 + tid];
    }
    __threadfence();
    __syncthreads();
    if (tid == 0) atomicOr(&g_done[bh], 1u << c);

    // ---- P2: wait for all earlier chunks of this bh ----
    unsigned need = (1u << c) - 1u;
    if (tid == 0 && need) {
        while ((atomicOr(&g_done[bh], 0u) & need) != need) __nanosleep(64);
    }
    __syncthreads();

    // ---- P3: qt = qf / cumsum(kf) ----
    {
        int f = tid & 63, hlf = tid >> 6;
        float base = 0.f;
        for (int c2 = 0; c2 < c; c2++)
            base += g_pK[((size_t)bh * NCH + c2) * 64 + f];
        float kc = base + (hlf ? part_s[f] : 0.f);   // part_s still holds half-sums
        for (int u = hlf * 32; u < hlf * 32 + 32; u++) {
            kc += kf_s[u * 64 + f];
            qt_s[u * 64 + f] = __fdividef(qt_s[u * 64 + f], kc);
        }
    }
    __syncthreads();

    // ---- P4: preS rebuild (batched MLP loads) + inter-chunk GEMM ----
    u64 acc[8][2] = {};
    if (c > 0) {
        float4 a4[8];
#pragma unroll
        for (int j = 0; j < 8; j++) a4[j] = make_float4(0.f, 0.f, 0.f, 0.f);
        const float4* base4 = (const float4*)(g_pS + (size_t)bh * NCH * 4096);
        for (int c2 = 0; c2 < c; c2++) {
#pragma unroll
            for (int j = 0; j < 8; j++) {
                float4 t = base4[c2 * 1024 + j * 128 + tid];
                a4[j].x += t.x; a4[j].y += t.y; a4[j].z += t.z; a4[j].w += t.w;
            }
        }
#pragma unroll
        for (int j = 0; j < 8; j++) ((float4*)X_s)[j * 128 + tid] = a4[j];
        __syncthreads();
#pragma unroll
        for (int k = 0; k < 64; k += 4)
            micro84p<64, 64>(qt_s, X_s, 8 * rt, 4 * ct, k, acc);
    }
    __syncthreads();

    // ---- P5: intra-chunk (scores, mask, @vp) ----
    {   // rebuild kf^T in X_s
        int u = tid >> 1, fb = (tid & 1) * 32;
#pragma unroll
        for (int j = 0; j < 32; j += 4) {
            float4 w = *(const float4*)&kf_s[u * 64 + fb + j];
            X_s[(fb + j + 0) * 64 + u] = w.x;
            X_s[(fb + j + 1) * 64 + u] = w.y;
            X_s[(fb + j + 2) * 64 + u] = w.z;
            X_s[(fb + j + 3) * 64 + u] = w.w;
        }
    }
    __syncthreads();
    u64 acc1[8][2] = {};
#pragma unroll
    for (int k = 0; k < 64; k += 4)
        micro84p<64, 64>(qt_s, X_s, 8 * rt, 4 * ct, k, acc1);
    __syncthreads();
#pragma unroll
    for (int i = 0; i < 8; i++) {
        int r = 8 * rt + i;
        float2 p0 = upk(acc1[i][0]), p1 = upk(acc1[i][1]);
        float4 vv;
        vv.x = (4 * ct + 0 <= r) ? p0.x : 0.f;
        vv.y = (4 * ct + 1 <= r) ? p0.y : 0.f;
        vv.z = (4 * ct + 2 <= r) ? p1.x : 0.f;
        vv.w = (4 * ct + 3 <= r) ? p1.y : 0.f;
        *(float4*)&X_s[r * 64 + 4 * ct] = vv;
    }
    __syncthreads();
#pragma unroll
    for (int k = 0; k < 64; k += 4)
        micro84p<64, 64>(X_s, vp_s, 8 * rt, 4 * ct, k, acc);

#pragma unroll
    for (int i = 0; i < 8; i++) {
        int s = c * CHUNK + 8 * rt + i;
        float2 p0 = upk(acc[i][0]), p1 = upk(acc[i][1]);
        *(float4*)&g_attn[((size_t)b * SEQ + s) * DMODEL + h * DEP + 4 * ct] =
            make_float4(p0.x, p0.y, p1.x, p1.y);
    }
    // publish attn rows for the fc blocks
    __threadfence();
    __syncthreads();
    if (tid == 0) atomicAdd(&g_adone[b * NCH + c], 1u);
}

// ---------------- launch ----------------
extern "C" void kernel_launch(void* const* d_in, const int* in_sizes, int n_in,
                              void* d_out, int out_size) {
    (void)in_sizes; (void)n_in; (void)out_size;
    const float* q    = (const float*)d_in[0];
    const float* k    = (const float*)d_in[1];
    const float* v    = (const float*)d_in[2];
    const float* Wq   = (const float*)d_in[3];
    const float* bq   = (const float*)d_in[4];
    const float* Wk   = (const float*)d_in[5];
    const float* bk   = (const float*)d_in[6];
    const float* Wv   = (const float*)d_in[7];
    const float* bv   = (const float*)d_in[8];
    const float* orfq = (const float*)d_in[9];
    const float* orfk = (const float*)d_in[10];
    const float* Wfc  = (const float*)d_in[11];
    const float* bfc  = (const float*)d_in[12];
    float* out = (float*)d_out;

    static bool attr_set = false;
    if (!attr_set) {
        cudaFuncSetAttribute(mega_fc_kernel, cudaFuncAttributeMaxDynamicSharedMemorySize, 81920);
        attr_set = true;
    }

    prep_kernel<<<11, 256>>>(Wq, bq, Wk, bk, orfq, orfk, Wv, Wfc);
    mega_fc_kernel<<<384, 128, 81920>>>(q, k, v, bv, bfc, out);
}

// round 9
// speedup vs baseline: 1.0847x; 1.0847x over previous
#include <cuda_runtime.h>

#define BATCH   2
#define SEQ     1024
#define HEADS   8
#define DEP     64
#define NF      64
#define BH      (BATCH*HEADS)   // 16
#define DMODEL  512
#define CHUNK   64
#define NCH     (SEQ/CHUNK)     // 16

typedef unsigned long long u64;

// ---------------- scratch (static device globals; no allocation) ----------------
__device__ float g_Mqt[DEP*NF];              // Mq transposed: [d][f]
__device__ float g_Mkt[DEP*NF];              // Mk transposed: [d][f]
__device__ float g_Wvt[DEP*DEP];             // Wv transposed: [d][e]
__device__ float g_cbq[NF];
__device__ float g_cbk[NF];
__device__ float g_pS[BH*NCH*NF*DEP];        // per-chunk sum of kf ⊗ vp
__device__ float g_pK[BH*NCH*NF];            // per-chunk sum of kf
__device__ float g_attn[BATCH*SEQ*DMODEL];   // attention out, [b][s][h*64+d]
__device__ unsigned g_done[BH];              // per-bh chunk-completion bitmask

// ---------------- packed f32x2 helpers (sm_103a FFMA2) ----------------
__device__ __forceinline__ u64 pk2(float x) {
    u64 r; asm("mov.b64 %0, {%1,%1};" : "=l"(r) : "f"(x)); return r;
}
__device__ __forceinline__ u64 pk2b(float x, float y) {
    u64 r; asm("mov.b64 %0, {%1,%2};" : "=l"(r) : "f"(x), "f"(y)); return r;
}
__device__ __forceinline__ void fma2(u64& d, u64 a, u64 b) {
    asm("fma.rn.f32x2 %0, %1, %2, %0;" : "+l"(d) : "l"(a), "l"(b));
}
__device__ __forceinline__ float2 upk(u64 v) {
    float2 f; asm("mov.b64 {%0,%1}, %2;" : "=f"(f.x), "=f"(f.y) : "l"(v)); return f;
}

// ---------------- 4x4 micro-kernel (prep) ----------------
template<int LDA, int LDB>
__device__ __forceinline__ void micro4p(const float* As, const float* Bs,
                                        int rb, int cb, int k, u64 acc[4][2]) {
    float a[4][4];
#pragma unroll
    for (int i = 0; i < 4; i++)
        *(float4*)a[i] = *(const float4*)&As[(rb + i) * LDA + k];
    u64 b[4][2];
#pragma unroll
    for (int kk = 0; kk < 4; kk++)
        *(ulonglong2*)b[kk] = *(const ulonglong2*)&Bs[(k + kk) * LDB + cb];
#pragma unroll
    for (int kk = 0; kk < 4; kk++)
#pragma unroll
        for (int i = 0; i < 4; i++) {
            u64 ad = pk2(a[i][kk]);
            fma2(acc[i][0], ad, b[kk][0]);
            fma2(acc[i][1], ad, b[kk][1]);
        }
}

// ---------------- 8x2 micro-kernel (mega @256thr): A-rows broadcast per warp ----------------
template<int LDA, int LDB>
__device__ __forceinline__ void micro82p(const float* As, const float* Bs,
                                         int rb, int cb, int k, u64 acc[8]) {
    float a[8][4];
#pragma unroll
    for (int i = 0; i < 8; i++)
        *(float4*)a[i] = *(const float4*)&As[(rb + i) * LDA + k];
#pragma unroll
    for (int kk = 0; kk < 4; kk++) {
        u64 b = *(const u64*)&Bs[(k + kk) * LDB + cb];
#pragma unroll
        for (int i = 0; i < 8; i++)
            fma2(acc[i], pk2(a[i][kk]), b);
    }
}

// ---------------- 8x4 micro-kernel (fc @256thr) ----------------
template<int LDA, int LDB>
__device__ __forceinline__ void micro84f(const float* As, const float* Bs,
                                         int rb, int cb, int k, u64 acc[8][2]) {
    float a[8][4];
#pragma unroll
    for (int i = 0; i < 8; i++)
        *(float4*)a[i] = *(const float4*)&As[(rb + i) * LDA + k];
#pragma unroll
    for (int kk = 0; kk < 4; kk++) {
        u64 b[2];
        *(ulonglong2*)b = *(const ulonglong2*)&Bs[(k + kk) * LDB + cb];
#pragma unroll
        for (int i = 0; i < 8; i++) {
            u64 ad = pk2(a[i][kk]);
            fma2(acc[i][0], ad, b[0]);
            fma2(acc[i][1], ad, b[1]);
        }
    }
}

// ---------------- K0: fold Linear+ORF (transposed), transpose Wv, reset flags ----------------
__global__ void prep_kernel(const float* __restrict__ Wq, const float* __restrict__ bq,
                            const float* __restrict__ Wk, const float* __restrict__ bk,
                            const float* __restrict__ orfq, const float* __restrict__ orfk,
                            const float* __restrict__ Wv) {
    int tid = threadIdx.x;
    if (blockIdx.x == 2) {   // Wv^T: g_Wvt[d][e] = Wv[e][d]
        for (int i = tid; i < 4096; i += 256) {
            int e = i >> 6, d = i & 63;
            g_Wvt[d * 64 + e] = Wv[i];
        }
        return;
    }
    __shared__ float orf_s[4096];   // [f][e]
    __shared__ float W_s[4096];     // [e][d]
    __shared__ float b_s[64];
    const float norm = 0.35355339059327379f;  // 64^(-0.25)
    int s = blockIdx.x;
    const float* orf = s ? orfk : orfq;
    const float* W   = s ? Wk   : Wq;
    const float* bb  = s ? bk   : bq;
    float* Mt = s ? g_Mkt : g_Mqt;
    float* cb = s ? g_cbk : g_cbq;
    if (s == 0 && tid < BH) g_done[tid] = 0u;   // reset each launch (graph replay)
    for (int i = tid; i < 1024; i += 256) {
        ((float4*)orf_s)[i] = ((const float4*)orf)[i];
        ((float4*)W_s)[i]   = ((const float4*)W)[i];
    }
    if (tid < 64) b_s[tid] = bb[tid];
    __syncthreads();

    int rt = tid >> 4, ct = tid & 15;
    u64 acc[4][2] = {};
#pragma unroll
    for (int k = 0; k < 64; k += 4)
        micro4p<64, 64>(orf_s, W_s, 4 * rt, 4 * ct, k, acc);
#pragma unroll
    for (int i = 0; i < 4; i++) {
        float2 p0 = upk(acc[i][0]), p1 = upk(acc[i][1]);
        float vals[4] = { p0.x, p0.y, p1.x, p1.y };
#pragma unroll
        for (int j = 0; j < 4; j++)          // transposed store: Mt[d][f]
            Mt[(4 * ct + j) * 64 + (4 * rt + i)] = norm * vals[j];
    }
    if (tid < 64) {
        float a = 0.f;
#pragma unroll
        for (int e = 0; e < 64; e++) a += orf_s[tid * 64 + e] * b_s[e];
        cb[tid] = norm * a;
    }
}

// ---------------- K1 (mega, 256 threads): features + partials + device-sync + output ----------------
// smem layout (floats): X_s[0..4096) scratch, w_s[4096..8192) weights,
// qt_s[8192..12288), kf_s[12288..16384), vp_s[16384..20480)  = 80KB
__global__ void __launch_bounds__(256) mega_kernel(const float* __restrict__ qin,
                                                   const float* __restrict__ kin,
                                                   const float* __restrict__ vin,
                                                   const float* __restrict__ bv) {
    extern __shared__ float sm[];
    float* X_s  = sm;
    float* w_s  = sm + 4096;
    float* qt_s = sm + 8192;
    float* kf_s = sm + 12288;
    float* vp_s = sm + 16384;
    __shared__ float part_s[256];

    int bh = blockIdx.x, c = blockIdx.y, tid = threadIdx.x;
    int b = bh >> 3, h = bh & 7;
    int rt = tid >> 5;            // 8 row-groups (warp-uniform -> A broadcast)
    int cb = (tid & 31) * 2;      // 2 cols per thread

    // ---- P0: feature GEMMs for this chunk (q, k, v) ----
#pragma unroll 1
    for (int str = 0; str < 3; str++) {
        const float* inp  = (str == 0) ? qin   : (str == 1) ? kin   : vin;
        const float* wt   = (str == 0) ? g_Mqt : (str == 1) ? g_Mkt : g_Wvt;
        const float* bias = (str == 0) ? g_cbq : (str == 1) ? g_cbk : bv;
        float* dst        = (str == 0) ? qt_s  : (str == 1) ? kf_s  : vp_s;
        const float4* ing = (const float4*)(inp + ((size_t)(b * SEQ + c * CHUNK)) * DMODEL + h * DEP);
        for (int i = tid; i < 1024; i += 256)
            ((float4*)X_s)[i] = ing[(i >> 4) * 128 + (i & 15)];   // [t][d]
        for (int i = tid; i < 1024; i += 256)
            ((float4*)w_s)[i] = ((const float4*)wt)[i];           // [d][out]
        __syncthreads();
        u64 acc[8];
        {
            u64 b0 = pk2b(bias[cb], bias[cb + 1]);
#pragma unroll
            for (int i = 0; i < 8; i++) acc[i] = b0;
        }
#pragma unroll
        for (int k = 0; k < 64; k += 4)
            micro82p<64, 64>(X_s, w_s, 8 * rt, cb, k, acc);
#pragma unroll
        for (int i = 0; i < 8; i++) {
            float2 p = upk(acc[i]);
            if (str < 2) {
                p.x = fmaxf(p.x, 0.f) + 0.001f;
                p.y = fmaxf(p.y, 0.f) + 0.001f;
            }
            *(float2*)&dst[(8 * rt + i) * 64 + cb] = p;
        }
        __syncthreads();
    }

    // ---- P1: kf^T into X_s, pK partials, pS GEMM; publish ----
    {
        int u = tid >> 2, fb = (tid & 3) * 16;
#pragma unroll
        for (int j = 0; j < 16; j += 4) {
            float4 w = *(const float4*)&kf_s[u * 64 + fb + j];
            X_s[(fb + j + 0) * 64 + u] = w.x;
            X_s[(fb + j + 1) * 64 + u] = w.y;
            X_s[(fb + j + 2) * 64 + u] = w.z;
            X_s[(fb + j + 3) * 64 + u] = w.w;
        }
    }
    {
        int f = tid & 63, qtr = tid >> 6;
        float ps = 0.f;
        for (int u = qtr * 16; u < qtr * 16 + 16; u++) ps += kf_s[u * 64 + f];
        part_s[qtr * 64 + f] = ps;
    }
    __syncthreads();
    {
        u64 acc2[8] = {};
#pragma unroll
        for (int k = 0; k < 64; k += 4)
            micro82p<64, 64>(X_s, vp_s, 8 * rt, cb, k, acc2);
        float* pS_out = g_pS + ((size_t)bh * NCH + c) * 4096;
#pragma unroll
        for (int i = 0; i < 8; i++) {
            float2 p = upk(acc2[i]);
            *(float2*)&pS_out[(8 * rt + i) * 64 + cb] = p;
        }
        if (tid < 64)
            g_pK[((size_t)bh * NCH + c) * 64 + tid] =
                part_s[tid] + part_s[64 + tid] + part_s[128 + tid] + part_s[192 + tid];
    }
    __threadfence();
    __syncthreads();
    if (tid == 0) atomicOr(&g_done[bh], 1u << c);

    // ---- P2: wait for all earlier chunks of this bh ----
    unsigned need = (1u << c) - 1u;
    if (tid == 0 && need) {
        while ((atomicOr(&g_done[bh], 0u) & need) != need) __nanosleep(64);
    }
    __syncthreads();

    // ---- P3: qt = qf / cumsum(kf), quarter-split ----
    {
        int f = tid & 63, qtr = tid >> 6;
        float base = 0.f;
        for (int c2 = 0; c2 < c; c2++)
            base += g_pK[((size_t)bh * NCH + c2) * 64 + f];
        float kc = base;
        for (int q2 = 0; q2 < qtr; q2++) kc += part_s[q2 * 64 + f];
        for (int u = qtr * 16; u < qtr * 16 + 16; u++) {
            kc += kf_s[u * 64 + f];
            qt_s[u * 64 + f] = __fdividef(qt_s[u * 64 + f], kc);
        }
    }
    __syncthreads();

    // ---- P4: preS rebuild (batched MLP loads) + inter-chunk GEMM ----
    u64 acc[8] = {};
    if (c > 0) {
        float4 a4[4];
#pragma unroll
        for (int j = 0; j < 4; j++) a4[j] = make_float4(0.f, 0.f, 0.f, 0.f);
        const float4* base4 = (const float4*)(g_pS + (size_t)bh * NCH * 4096);
        for (int c2 = 0; c2 < c; c2++) {
#pragma unroll
            for (int j = 0; j < 4; j++) {
                float4 t = base4[c2 * 1024 + j * 256 + tid];
                a4[j].x += t.x; a4[j].y += t.y; a4[j].z += t.z; a4[j].w += t.w;
            }
        }
#pragma unroll
        for (int j = 0; j < 4; j++) ((float4*)X_s)[j * 256 + tid] = a4[j];
        __syncthreads();
#pragma unroll
        for (int k = 0; k < 64; k += 4)
            micro82p<64, 64>(qt_s, X_s, 8 * rt, cb, k, acc);
    }
    __syncthreads();

    // ---- P5: intra-chunk (scores, mask, @vp) ----
    {   // rebuild kf^T in X_s
        int u = tid >> 2, fb = (tid & 3) * 16;
#pragma unroll
        for (int j = 0; j < 16; j += 4) {
            float4 w = *(const float4*)&kf_s[u * 64 + fb + j];
            X_s[(fb + j + 0) * 64 + u] = w.x;
            X_s[(fb + j + 1) * 64 + u] = w.y;
            X_s[(fb + j + 2) * 64 + u] = w.z;
            X_s[(fb + j + 3) * 64 + u] = w.w;
        }
    }
    __syncthreads();
    u64 acc1[8] = {};
#pragma unroll
    for (int k = 0; k < 64; k += 4)
        micro82p<64, 64>(qt_s, X_s, 8 * rt, cb, k, acc1);
    __syncthreads();
#pragma unroll
    for (int i = 0; i < 8; i++) {
        int r = 8 * rt + i;
        float2 p = upk(acc1[i]);
        float2 vv;
        vv.x = (cb + 0 <= r) ? p.x : 0.f;
        vv.y = (cb + 1 <= r) ? p.y : 0.f;
        *(float2*)&X_s[r * 64 + cb] = vv;
    }
    __syncthreads();
#pragma unroll
    for (int k = 0; k < 64; k += 4)
        micro82p<64, 64>(X_s, vp_s, 8 * rt, cb, k, acc);

#pragma unroll
    for (int i = 0; i < 8; i++) {
        int s = c * CHUNK + 8 * rt + i;
        float2 p = upk(acc[i]);
        *(float2*)&g_attn[((size_t)b * SEQ + s) * DMODEL + h * DEP + cb] = p;
    }
}

// ---------------- K2: fc one-pass  out = attn @ Wfc^T + bfc  (64x128 tiles, full K) ----------------
__global__ void __launch_bounds__(256) fc_kernel(const float* __restrict__ Wfc,
                                                 const float* __restrict__ bfc,
                                                 float* __restrict__ out) {
    __shared__ float A_s[64 * 32];
    __shared__ float Bt_s[32 * 128];   // [e][o]
    int tid = threadIdx.x;
    int r0 = blockIdx.x * 64, o0 = blockIdx.y * 128;
    int rt = tid >> 5;              // 8 row-groups of 8 (warp-uniform)
    int cb = (tid & 31) * 4;        // 4 cols per thread
    u64 acc[8][2];
    {
        u64 b0 = pk2b(bfc[o0 + cb + 0], bfc[o0 + cb + 1]);
        u64 b1 = pk2b(bfc[o0 + cb + 2], bfc[o0 + cb + 3]);
#pragma unroll
        for (int i = 0; i < 8; i++) { acc[i][0] = b0; acc[i][1] = b1; }
    }
    for (int kt = 0; kt < DMODEL; kt += 32) {
        for (int i = tid; i < 512; i += 256) {
            int r = i >> 3, kk4 = (i & 7) * 4;
            *(float4*)&A_s[r * 32 + kk4] =
                *(const float4*)&g_attn[(size_t)(r0 + r) * DMODEL + kt + kk4];
        }
        for (int i = tid; i < 1024; i += 256) {
            int o = i >> 3, ee4 = (i & 7) * 4;
            float4 w = *(const float4*)&Wfc[(size_t)(o0 + o) * DMODEL + kt + ee4];
            Bt_s[(ee4 + 0) * 128 + o] = w.x;
            Bt_s[(ee4 + 1) * 128 + o] = w.y;
            Bt_s[(ee4 + 2) * 128 + o] = w.z;
            Bt_s[(ee4 + 3) * 128 + o] = w.w;
        }
        __syncthreads();
#pragma unroll
        for (int k = 0; k < 32; k += 4)
            micro84f<32, 128>(A_s, Bt_s, 8 * rt, cb, k, acc);
        __syncthreads();
    }
#pragma unroll
    for (int i = 0; i < 8; i++) {
        int r = r0 + 8 * rt + i;
        float2 p0 = upk(acc[i][0]), p1 = upk(acc[i][1]);
        *(float4*)&out[(size_t)r * DMODEL + o0 + cb] = make_float4(p0.x, p0.y, p1.x, p1.y);
    }
}

// ---------------- launch ----------------
extern "C" void kernel_launch(void* const* d_in, const int* in_sizes, int n_in,
                              void* d_out, int out_size) {
    (void)in_sizes; (void)n_in; (void)out_size;
    const float* q    = (const float*)d_in[0];
    const float* k    = (const float*)d_in[1];
    const float* v    = (const float*)d_in[2];
    const float* Wq   = (const float*)d_in[3];
    const float* bq   = (const float*)d_in[4];
    const float* Wk   = (const float*)d_in[5];
    const float* bk   = (const float*)d_in[6];
    const float* Wv   = (const float*)d_in[7];
    const float* bv   = (const float*)d_in[8];
    const float* orfq = (const float*)d_in[9];
    const float* orfk = (const float*)d_in[10];
    const float* Wfc  = (const float*)d_in[11];
    const float* bfc  = (const float*)d_in[12];
    float* out = (float*)d_out;

    static bool attr_set = false;
    if (!attr_set) {
        cudaFuncSetAttribute(mega_kernel, cudaFuncAttributeMaxDynamicSharedMemorySize, 81920);
        attr_set = true;
    }

    prep_kernel<<<3, 256>>>(Wq, bq, Wk, bk, orfq, orfk, Wv);
    mega_kernel<<<dim3(BH, NCH), 256, 81920>>>(q, k, v, bv);
    fc_kernel<<<dim3(SEQ * BATCH / 64, DMODEL / 128), 256>>>(Wfc, bfc, out);
}

// round 10
// speedup vs baseline: 1.1574x; 1.0670x over previous
#include <cuda_runtime.h>

#define BATCH   2
#define SEQ     1024
#define HEADS   8
#define DEP     64
#define NF      64
#define BH      (BATCH*HEADS)   // 16
#define DMODEL  512
#define CHUNK   64
#define NCH     (SEQ/CHUNK)     // 16

typedef unsigned long long u64;

// ---------------- scratch (static device globals; no allocation) ----------------
__device__ float g_Mqt[DEP*NF];              // Mq transposed: [d][f]
__device__ float g_Mkt[DEP*NF];              // Mk transposed: [d][f]
__device__ float g_Wvt[DEP*DEP];             // Wv transposed: [d][e]
__device__ float g_cbq[NF];
__device__ float g_cbk[NF];
__device__ float g_pS[BH*NCH*NF*DEP];        // per-chunk sum of kf ⊗ vp
__device__ float g_pK[BH*NCH*NF];            // per-chunk sum of kf
__device__ float g_attn[BATCH*SEQ*DMODEL];   // attention out, [b][s][h*64+d]
__device__ unsigned g_done[BH];              // per-bh chunk-completion bitmask

// ---------------- packed f32x2 helpers (sm_103a FFMA2) ----------------
__device__ __forceinline__ u64 pk2(float x) {
    u64 r; asm("mov.b64 %0, {%1,%1};" : "=l"(r) : "f"(x)); return r;
}
__device__ __forceinline__ u64 pk2b(float x, float y) {
    u64 r; asm("mov.b64 %0, {%1,%2};" : "=l"(r) : "f"(x), "f"(y)); return r;
}
__device__ __forceinline__ void fma2(u64& d, u64 a, u64 b) {
    asm("fma.rn.f32x2 %0, %1, %2, %0;" : "+l"(d) : "l"(a), "l"(b));
}
__device__ __forceinline__ float2 upk(u64 v) {
    float2 f; asm("mov.b64 {%0,%1}, %2;" : "=f"(f.x), "=f"(f.y) : "l"(v)); return f;
}

// ---------------- 8x4 micro-kernel (mega GEMMs, 128 threads) ----------------
template<int LDA, int LDB>
__device__ __forceinline__ void micro84p(const float* As, const float* Bs,
                                         int rb, int cb, int k, u64 acc[8][2]) {
    float a[8][4];
#pragma unroll
    for (int i = 0; i < 8; i++)
        *(float4*)a[i] = *(const float4*)&As[(rb + i) * LDA + k];
#pragma unroll
    for (int kk = 0; kk < 4; kk++) {
        u64 b[2];
        *(ulonglong2*)b = *(const ulonglong2*)&Bs[(k + kk) * LDB + cb];
#pragma unroll
        for (int i = 0; i < 8; i++) {
            u64 ad = pk2(a[i][kk]);
            fma2(acc[i][0], ad, b[0]);
            fma2(acc[i][1], ad, b[1]);
        }
    }
}

// ---------------- 8x4 micro-kernel (fc @256thr, warp-uniform rows) ----------------
template<int LDA, int LDB>
__device__ __forceinline__ void micro84f(const float* As, const float* Bs,
                                         int rb, int cb, int k, u64 acc[8][2]) {
    float a[8][4];
#pragma unroll
    for (int i = 0; i < 8; i++)
        *(float4*)a[i] = *(const float4*)&As[(rb + i) * LDA + k];
#pragma unroll
    for (int kk = 0; kk < 4; kk++) {
        u64 b[2];
        *(ulonglong2*)b = *(const ulonglong2*)&Bs[(k + kk) * LDB + cb];
#pragma unroll
        for (int i = 0; i < 8; i++) {
            u64 ad = pk2(a[i][kk]);
            fma2(acc[i][0], ad, b[0]);
            fma2(acc[i][1], ad, b[1]);
        }
    }
}

// ---------------- K0: wide-parallel prep ----------------
// bids 0..15: fold M = norm*(orf@W) rows (s = bid&1 stream, 8 output rows per block).
// bid 16: Wv^T + g_done reset.
__global__ void __launch_bounds__(256) prep_kernel(
        const float* __restrict__ Wq, const float* __restrict__ bq,
        const float* __restrict__ Wk, const float* __restrict__ bk,
        const float* __restrict__ orfq, const float* __restrict__ orfk,
        const float* __restrict__ Wv) {
    int tid = threadIdx.x, bid = blockIdx.x;
    if (bid == 16) {   // Wv^T: g_Wvt[d][e] = Wv[e][d]; reset flags
        if (tid < BH) g_done[tid] = 0u;
        for (int i = tid; i < 1024; i += 256) {
            float4 w = ((const float4*)Wv)[i];      // Wv[e][d4..d4+3]
            int e = i >> 4, d4 = (i & 15) * 4;
            g_Wvt[(d4 + 0) * 64 + e] = w.x;
            g_Wvt[(d4 + 1) * 64 + e] = w.y;
            g_Wvt[(d4 + 2) * 64 + e] = w.z;
            g_Wvt[(d4 + 3) * 64 + e] = w.w;
        }
        return;
    }
    __shared__ float W_s[4096];     // [e][d]
    __shared__ float orf_s[8*64];   // 8 rows of orf
    __shared__ float b_s[64];
    const float norm = 0.35355339059327379f;  // 64^(-0.25)
    int s = bid & 1, rblk = bid >> 1;
    int f0 = rblk * 8;
    const float* orf = s ? orfk : orfq;
    const float* W   = s ? Wk   : Wq;
    const float* bb  = s ? bk   : bq;
    float* Mt = s ? g_Mkt : g_Mqt;
    float* cb = s ? g_cbk : g_cbq;
    for (int i = tid; i < 1024; i += 256)
        ((float4*)W_s)[i] = ((const float4*)W)[i];
    if (tid < 128)
        ((float4*)orf_s)[tid] = ((const float4*)(orf + f0 * 64))[tid];
    if (tid < 64) b_s[tid] = bb[tid];
    __syncthreads();

    int fr = tid >> 5;              // local row 0..7 (warp-uniform)
    int d2 = (tid & 31) * 2;        // 2 cols per thread
    u64 acc = 0;
#pragma unroll
    for (int e = 0; e < 64; e++)
        fma2(acc, pk2(orf_s[fr * 64 + e]), *(const u64*)&W_s[e * 64 + d2]);
    float2 p = upk(acc);
    Mt[(d2 + 0) * 64 + f0 + fr] = norm * p.x;   // transposed store: Mt[d][f]
    Mt[(d2 + 1) * 64 + f0 + fr] = norm * p.y;
    if (tid < 8) {
        float a = 0.f;
#pragma unroll
        for (int e = 0; e < 64; e++) a += orf_s[tid * 64 + e] * b_s[e];
        cb[f0 + tid] = norm * a;
    }
}

// ---------------- K1 (mega, 128 threads): features + partials + device-sync + output ----------------
// smem layout (floats): X_s[0..4096) scratch, w_s[4096..8192) weights,
// qt_s[8192..12288), kf_s[12288..16384), vp_s[16384..20480)  = 80KB
__global__ void __launch_bounds__(128) mega_kernel(const float* __restrict__ qin,
                                                   const float* __restrict__ kin,
                                                   const float* __restrict__ vin,
                                                   const float* __restrict__ bv) {
    extern __shared__ float sm[];
    float* X_s  = sm;
    float* w_s  = sm + 4096;
    float* qt_s = sm + 8192;
    float* kf_s = sm + 12288;
    float* vp_s = sm + 16384;
    __shared__ float part_s[128];

    int bh = blockIdx.x, c = blockIdx.y, tid = threadIdx.x;
    int b = bh >> 3, h = bh & 7;
    int rt = tid >> 4, ct = tid & 15;

    // ---- P0: feature GEMMs for this chunk (q, k, v) ----
#pragma unroll 1
    for (int str = 0; str < 3; str++) {
        const float* inp  = (str == 0) ? qin   : (str == 1) ? kin   : vin;
        const float* wt   = (str == 0) ? g_Mqt : (str == 1) ? g_Mkt : g_Wvt;
        const float* bias = (str == 0) ? g_cbq : (str == 1) ? g_cbk : bv;
        float* dst        = (str == 0) ? qt_s  : (str == 1) ? kf_s  : vp_s;
        const float4* ing = (const float4*)(inp + ((size_t)(b * SEQ + c * CHUNK)) * DMODEL + h * DEP);
        for (int i = tid; i < 1024; i += 128)
            ((float4*)X_s)[i] = ing[(i >> 4) * 128 + (i & 15)];   // [t][d]
        for (int i = tid; i < 1024; i += 128)
            ((float4*)w_s)[i] = ((const float4*)wt)[i];           // [d][out]
        __syncthreads();
        u64 acc[8][2];
        {
            u64 b0 = pk2b(bias[4 * ct + 0], bias[4 * ct + 1]);
            u64 b1 = pk2b(bias[4 * ct + 2], bias[4 * ct + 3]);
#pragma unroll
            for (int i = 0; i < 8; i++) { acc[i][0] = b0; acc[i][1] = b1; }
        }
#pragma unroll
        for (int k = 0; k < 64; k += 4)
            micro84p<64, 64>(X_s, w_s, 8 * rt, 4 * ct, k, acc);
#pragma unroll
        for (int i = 0; i < 8; i++) {
            int row = 8 * rt + i;
            float2 p0 = upk(acc[i][0]), p1 = upk(acc[i][1]);
            float4 vv = make_float4(p0.x, p0.y, p1.x, p1.y);
            if (str < 2) {
                vv.x = fmaxf(vv.x, 0.f) + 0.001f;
                vv.y = fmaxf(vv.y, 0.f) + 0.001f;
                vv.z = fmaxf(vv.z, 0.f) + 0.001f;
                vv.w = fmaxf(vv.w, 0.f) + 0.001f;
            }
            *(float4*)&dst[row * 64 + 4 * ct] = vv;
        }
        __syncthreads();
    }

    // ---- P1: kf^T into X_s, pK partials, pS GEMM; publish ----
    {
        int u = tid >> 1, fb = (tid & 1) * 32;
#pragma unroll
        for (int j = 0; j < 32; j += 4) {
            float4 w = *(const float4*)&kf_s[u * 64 + fb + j];
            X_s[(fb + j + 0) * 64 + u] = w.x;
            X_s[(fb + j + 1) * 64 + u] = w.y;
            X_s[(fb + j + 2) * 64 + u] = w.z;
            X_s[(fb + j + 3) * 64 + u] = w.w;
        }
    }
    {
        int f = tid & 63, hlf = tid >> 6;
        float ps = 0.f;
        for (int u = hlf * 32; u < hlf * 32 + 32; u++) ps += kf_s[u * 64 + f];
        part_s[hlf * 64 + f] = ps;
    }
    __syncthreads();
    {
        u64 acc2[8][2] = {};
#pragma unroll
        for (int k = 0; k < 64; k += 4)
            micro84p<64, 64>(X_s, vp_s, 8 * rt, 4 * ct, k, acc2);
        float* pS_out = g_pS + ((size_t)bh * NCH + c) * 4096;
#pragma unroll
        for (int i = 0; i < 8; i++) {
            float2 p0 = upk(acc2[i][0]), p1 = upk(acc2[i][1]);
            *(float4*)&pS_out[(8 * rt + i) * 64 + 4 * ct] = make_float4(p0.x, p0.y, p1.x, p1.y);
        }
        if (tid < 64)
            g_pK[((size_t)bh * NCH + c) * 64 + tid] = part_s[tid] + part_s[64 + tid];
    }
    __threadfence();
    __syncthreads();
    if (tid == 0) atomicOr(&g_done[bh], 1u << c);

    // ---- P2: wait for all earlier chunks of this bh ----
    unsigned need = (1u << c) - 1u;
    if (tid == 0 && need) {
        while ((atomicOr(&g_done[bh], 0u) & need) != need) __nanosleep(64);
    }
    __syncthreads();

    // ---- P3: qt = qf / cumsum(kf) ----
    {
        int f = tid & 63, hlf = tid >> 6;
        float base = 0.f;
        for (int c2 = 0; c2 < c; c2++)
            base += g_pK[((size_t)bh * NCH + c2) * 64 + f];
        float kc = base + (hlf ? part_s[f] : 0.f);   // part_s still holds half-sums
        for (int u = hlf * 32; u < hlf * 32 + 32; u++) {
            kc += kf_s[u * 64 + f];
            qt_s[u * 64 + f] = __fdividef(qt_s[u * 64 + f], kc);
        }
    }
    __syncthreads();

    // ---- P4: preS rebuild (batched MLP loads) + inter-chunk GEMM ----
    u64 acc[8][2] = {};
    if (c > 0) {
        float4 a4[8];
#pragma unroll
        for (int j = 0; j < 8; j++) a4[j] = make_float4(0.f, 0.f, 0.f, 0.f);
        const float4* base4 = (const float4*)(g_pS + (size_t)bh * NCH * 4096);
        for (int c2 = 0; c2 < c; c2++) {
#pragma unroll
            for (int j = 0; j < 8; j++) {
                float4 t = base4[c2 * 1024 + j * 128 + tid];
                a4[j].x += t.x; a4[j].y += t.y; a4[j].z += t.z; a4[j].w += t.w;
            }
        }
#pragma unroll
        for (int j = 0; j < 8; j++) ((float4*)X_s)[j * 128 + tid] = a4[j];
        __syncthreads();
#pragma unroll
        for (int k = 0; k < 64; k += 4)
            micro84p<64, 64>(qt_s, X_s, 8 * rt, 4 * ct, k, acc);
    }
    __syncthreads();

    // ---- P5: intra-chunk (scores, mask, @vp) ----
    {   // rebuild kf^T in X_s
        int u = tid >> 1, fb = (tid & 1) * 32;
#pragma unroll
        for (int j = 0; j < 32; j += 4) {
            float4 w = *(const float4*)&kf_s[u * 64 + fb + j];
            X_s[(fb + j + 0) * 64 + u] = w.x;
            X_s[(fb + j + 1) * 64 + u] = w.y;
            X_s[(fb + j + 2) * 64 + u] = w.z;
            X_s[(fb + j + 3) * 64 + u] = w.w;
        }
    }
    __syncthreads();
    u64 acc1[8][2] = {};
#pragma unroll
    for (int k = 0; k < 64; k += 4)
        micro84p<64, 64>(qt_s, X_s, 8 * rt, 4 * ct, k, acc1);
    __syncthreads();
#pragma unroll
    for (int i = 0; i < 8; i++) {
        int r = 8 * rt + i;
        float2 p0 = upk(acc1[i][0]), p1 = upk(acc1[i][1]);
        float4 vv;
        vv.x = (4 * ct + 0 <= r) ? p0.x : 0.f;
        vv.y = (4 * ct + 1 <= r) ? p0.y : 0.f;
        vv.z = (4 * ct + 2 <= r) ? p1.x : 0.f;
        vv.w = (4 * ct + 3 <= r) ? p1.y : 0.f;
        *(float4*)&X_s[r * 64 + 4 * ct] = vv;
    }
    __syncthreads();
#pragma unroll
    for (int k = 0; k < 64; k += 4)
        micro84p<64, 64>(X_s, vp_s, 8 * rt, 4 * ct, k, acc);

#pragma unroll
    for (int i = 0; i < 8; i++) {
        int s = c * CHUNK + 8 * rt + i;
        float2 p0 = upk(acc[i][0]), p1 = upk(acc[i][1]);
        *(float4*)&g_attn[((size_t)b * SEQ + s) * DMODEL + h * DEP + 4 * ct] =
            make_float4(p0.x, p0.y, p1.x, p1.y);
    }
}

// ---------------- K2: fc one-pass  out = attn @ Wfc^T + bfc  (64x128 tiles, full K) ----------------
__global__ void __launch_bounds__(256) fc_kernel(const float* __restrict__ Wfc,
                                                 const float* __restrict__ bfc,
                                                 float* __restrict__ out) {
    __shared__ float A_s[64 * 32];
    __shared__ float Bt_s[32 * 128];   // [e][o]
    int tid = threadIdx.x;
    int r0 = blockIdx.x * 64, o0 = blockIdx.y * 128;
    int rt = tid >> 5;              // 8 row-groups of 8 (warp-uniform -> A broadcast)
    int cb = (tid & 31) * 4;        // 4 cols per thread
    u64 acc[8][2];
    {
        u64 b0 = pk2b(bfc[o0 + cb + 0], bfc[o0 + cb + 1]);
        u64 b1 = pk2b(bfc[o0 + cb + 2], bfc[o0 + cb + 3]);
#pragma unroll
        for (int i = 0; i < 8; i++) { acc[i][0] = b0; acc[i][1] = b1; }
    }
    for (int kt = 0; kt < DMODEL; kt += 32) {
        for (int i = tid; i < 512; i += 256) {
            int r = i >> 3, kk4 = (i & 7) * 4;
            *(float4*)&A_s[r * 32 + kk4] =
                *(const float4*)&g_attn[(size_t)(r0 + r) * DMODEL + kt + kk4];
        }
        for (int i = tid; i < 1024; i += 256) {
            int o = i >> 3, ee4 = (i & 7) * 4;
            float4 w = *(const float4*)&Wfc[(size_t)(o0 + o) * DMODEL + kt + ee4];
            Bt_s[(ee4 + 0) * 128 + o] = w.x;
            Bt_s[(ee4 + 1) * 128 + o] = w.y;
            Bt_s[(ee4 + 2) * 128 + o] = w.z;
            Bt_s[(ee4 + 3) * 128 + o] = w.w;
        }
        __syncthreads();
#pragma unroll
        for (int k = 0; k < 32; k += 4)
            micro84f<32, 128>(A_s, Bt_s, 8 * rt, cb, k, acc);
        __syncthreads();
    }
#pragma unroll
    for (int i = 0; i < 8; i++) {
        int r = r0 + 8 * rt + i;
        float2 p0 = upk(acc[i][0]), p1 = upk(acc[i][1]);
        *(float4*)&out[(size_t)r * DMODEL + o0 + cb] = make_float4(p0.x, p0.y, p1.x, p1.y);
    }
}

// ---------------- launch ----------------
extern "C" void kernel_launch(void* const* d_in, const int* in_sizes, int n_in,
                              void* d_out, int out_size) {
    (void)in_sizes; (void)n_in; (void)out_size;
    const float* q    = (const float*)d_in[0];
    const float* k    = (const float*)d_in[1];
    const float* v    = (const float*)d_in[2];
    const float* Wq   = (const float*)d_in[3];
    const float* bq   = (const float*)d_in[4];
    const float* Wk   = (const float*)d_in[5];
    const float* bk   = (const float*)d_in[6];
    const float* Wv   = (const float*)d_in[7];
    const float* bv   = (const float*)d_in[8];
    const float* orfq = (const float*)d_in[9];
    const float* orfk = (const float*)d_in[10];
    const float* Wfc  = (const float*)d_in[11];
    const float* bfc  = (const float*)d_in[12];
    float* out = (float*)d_out;

    static bool attr_set = false;
    if (!attr_set) {
        cudaFuncSetAttribute(mega_kernel, cudaFuncAttributeMaxDynamicSharedMemorySize, 81920);
        attr_set = true;
    }

    prep_kernel<<<17, 256>>>(Wq, bq, Wk, bk, orfq, orfk, Wv);
    mega_kernel<<<dim3(BH, NCH), 128, 81920>>>(q, k, v, bv);
    fc_kernel<<<dim3(SEQ * BATCH / 64, DMODEL / 128), 256>>>(Wfc, bfc, out);
}

// round 12
// speedup vs baseline: 1.2733x; 1.1002x over previous
#include <cuda_runtime.h>

#define BATCH   2
#define SEQ     1024
#define HEADS   8
#define DEP     64
#define NF      64
#define BH      (BATCH*HEADS)   // 16
#define DMODEL  512
#define CHUNK   64
#define NCH     (SEQ/CHUNK)     // 16

typedef unsigned long long u64;

// ---------------- scratch (static device globals; no allocation) ----------------
__device__ float g_Mqt[DEP*NF];              // Mq transposed: [d][f]
__device__ float g_Mkt[DEP*NF];              // Mk transposed: [d][f]
__device__ float g_Wvt[DEP*DEP];             // Wv transposed: [d][e]
__device__ float g_cbq[NF];
__device__ float g_cbk[NF];
__device__ float g_pS[BH*NCH*NF*DEP];        // per-chunk sum of kf ⊗ vp
__device__ float g_pK[BH*NCH*NF];            // per-chunk sum of kf
__device__ float g_attn[BATCH*SEQ*DMODEL];   // attention out, [b][s][h*64+d]
__device__ unsigned g_done[BH];              // per-bh chunk-completion bitmask
__device__ unsigned g_adone[BATCH*NCH];      // per-(b,c) attn completion counter (8 heads)

// ---------------- packed f32x2 helpers (sm_103a FFMA2) ----------------
__device__ __forceinline__ u64 pk2(float x) {
    u64 r; asm("mov.b64 %0, {%1,%1};" : "=l"(r) : "f"(x)); return r;
}
__device__ __forceinline__ u64 pk2b(float x, float y) {
    u64 r; asm("mov.b64 %0, {%1,%2};" : "=l"(r) : "f"(x), "f"(y)); return r;
}
__device__ __forceinline__ void fma2(u64& d, u64 a, u64 b) {
    asm("fma.rn.f32x2 %0, %1, %2, %0;" : "+l"(d) : "l"(a), "l"(b));
}
__device__ __forceinline__ float2 upk(u64 v) {
    float2 f; asm("mov.b64 {%0,%1}, %2;" : "=f"(f.x), "=f"(f.y) : "l"(v)); return f;
}

// ---------------- 8x4 micro-kernel (mega GEMMs, 128 threads) ----------------
template<int LDA, int LDB>
__device__ __forceinline__ void micro84p(const float* As, const float* Bs,
                                         int rb, int cb, int k, u64 acc[8][2]) {
    float a[8][4];
#pragma unroll
    for (int i = 0; i < 8; i++)
        *(float4*)a[i] = *(const float4*)&As[(rb + i) * LDA + k];
#pragma unroll
    for (int kk = 0; kk < 4; kk++) {
        u64 b[2];
        *(ulonglong2*)b = *(const ulonglong2*)&Bs[(k + kk) * LDB + cb];
#pragma unroll
        for (int i = 0; i < 8; i++) {
            u64 ad = pk2(a[i][kk]);
            fma2(acc[i][0], ad, b[0]);
            fma2(acc[i][1], ad, b[1]);
        }
    }
}

// ---------------- K0: wide-parallel prep ----------------
// bids 0..15: fold M = norm*(orf@W) rows (s = bid&1 stream, 8 output rows per block).
// bid 16: Wv^T + flag resets.
__global__ void __launch_bounds__(256) prep_kernel(
        const float* __restrict__ Wq, const float* __restrict__ bq,
        const float* __restrict__ Wk, const float* __restrict__ bk,
        const float* __restrict__ orfq, const float* __restrict__ orfk,
        const float* __restrict__ Wv) {
    int tid = threadIdx.x, bid = blockIdx.x;
    if (bid == 16) {   // Wv^T: g_Wvt[d][e] = Wv[e][d]; reset flags
        if (tid < BH) g_done[tid] = 0u;
        if (tid < BATCH * NCH) g_adone[tid] = 0u;
        for (int i = tid; i < 1024; i += 256) {
            float4 w = ((const float4*)Wv)[i];      // Wv[e][d4..d4+3]
            int e = i >> 4, d4 = (i & 15) * 4;
            g_Wvt[(d4 + 0) * 64 + e] = w.x;
            g_Wvt[(d4 + 1) * 64 + e] = w.y;
            g_Wvt[(d4 + 2) * 64 + e] = w.z;
            g_Wvt[(d4 + 3) * 64 + e] = w.w;
        }
        return;
    }
    __shared__ float W_s[4096];     // [e][d]
    __shared__ float orf_s[8*64];   // 8 rows of orf
    __shared__ float b_s[64];
    const float norm = 0.35355339059327379f;  // 64^(-0.25)
    int s = bid & 1, rblk = bid >> 1;
    int f0 = rblk * 8;
    const float* orf = s ? orfk : orfq;
    const float* W   = s ? Wk   : Wq;
    const float* bb  = s ? bk   : bq;
    float* Mt = s ? g_Mkt : g_Mqt;
    float* cb = s ? g_cbk : g_cbq;
    for (int i = tid; i < 1024; i += 256)
        ((float4*)W_s)[i] = ((const float4*)W)[i];
    if (tid < 128)
        ((float4*)orf_s)[tid] = ((const float4*)(orf + f0 * 64))[tid];
    if (tid < 64) b_s[tid] = bb[tid];
    __syncthreads();

    int fr = tid >> 5;              // local row 0..7 (warp-uniform)
    int d2 = (tid & 31) * 2;        // 2 cols per thread
    u64 acc = 0;
#pragma unroll
    for (int e = 0; e < 64; e++)
        fma2(acc, pk2(orf_s[fr * 64 + e]), *(const u64*)&W_s[e * 64 + d2]);
    float2 p = upk(acc);
    Mt[(d2 + 0) * 64 + f0 + fr] = norm * p.x;   // transposed store: Mt[d][f]
    Mt[(d2 + 1) * 64 + f0 + fr] = norm * p.y;
    if (tid < 8) {
        float a = 0.f;
#pragma unroll
        for (int e = 0; e < 64; e++) a += orf_s[tid * 64 + e] * b_s[e];
        cb[f0 + tid] = norm * a;
    }
}

// ---------------- K1 (mega, 128 threads): features + partials + device-sync + output + fused fc ----------------
// smem layout (floats): X_s[0..4096) scratch, w_s[4096..8192) weights,
// qt_s[8192..12288), kf_s[12288..16384), vp_s[16384..20480)  = 80KB
__global__ void __launch_bounds__(128) mega_kernel(const float* __restrict__ qin,
                                                   const float* __restrict__ kin,
                                                   const float* __restrict__ vin,
                                                   const float* __restrict__ bv,
                                                   const float* __restrict__ Wfc,
                                                   const float* __restrict__ bfc,
                                                   float* __restrict__ out) {
    extern __shared__ float sm[];
    float* X_s  = sm;
    float* w_s  = sm + 4096;
    float* qt_s = sm + 8192;
    float* kf_s = sm + 12288;
    float* vp_s = sm + 16384;
    __shared__ float part_s[128];

    int bh = blockIdx.x, c = blockIdx.y, tid = threadIdx.x;
    int b = bh >> 3, h = bh & 7;
    int rt = tid >> 4, ct = tid & 15;

    // ---- P0: feature GEMMs for this chunk (q, k, v) ----
#pragma unroll 1
    for (int str = 0; str < 3; str++) {
        const float* inp  = (str == 0) ? qin   : (str == 1) ? kin   : vin;
        const float* wt   = (str == 0) ? g_Mqt : (str == 1) ? g_Mkt : g_Wvt;
        const float* bias = (str == 0) ? g_cbq : (str == 1) ? g_cbk : bv;
        float* dst        = (str == 0) ? qt_s  : (str == 1) ? kf_s  : vp_s;
        const float4* ing = (const float4*)(inp + ((size_t)(b * SEQ + c * CHUNK)) * DMODEL + h * DEP);
        for (int i = tid; i < 1024; i += 128)
            ((float4*)X_s)[i] = ing[(i >> 4) * 128 + (i & 15)];   // [t][d]
        for (int i = tid; i < 1024; i += 128)
            ((float4*)w_s)[i] = ((const float4*)wt)[i];           // [d][out]
        __syncthreads();
        u64 acc[8][2];
        {
            u64 b0 = pk2b(bias[4 * ct + 0], bias[4 * ct + 1]);
            u64 b1 = pk2b(bias[4 * ct + 2], bias[4 * ct + 3]);
#pragma unroll
            for (int i = 0; i < 8; i++) { acc[i][0] = b0; acc[i][1] = b1; }
        }
#pragma unroll
        for (int k = 0; k < 64; k += 4)
            micro84p<64, 64>(X_s, w_s, 8 * rt, 4 * ct, k, acc);
#pragma unroll
        for (int i = 0; i < 8; i++) {
            int row = 8 * rt + i;
            float2 p0 = upk(acc[i][0]), p1 = upk(acc[i][1]);
            float4 vv = make_float4(p0.x, p0.y, p1.x, p1.y);
            if (str < 2) {
                vv.x = fmaxf(vv.x, 0.f) + 0.001f;
                vv.y = fmaxf(vv.y, 0.f) + 0.001f;
                vv.z = fmaxf(vv.z, 0.f) + 0.001f;
                vv.w = fmaxf(vv.w, 0.f) + 0.001f;
            }
            *(float4*)&dst[row * 64 + 4 * ct] = vv;
        }
        __syncthreads();
    }

    // ---- P1: kf^T into X_s, pK partials, pS GEMM; publish ----
    {
        int u = tid >> 1, fb = (tid & 1) * 32;
#pragma unroll
        for (int j = 0; j < 32; j += 4) {
            float4 w = *(const float4*)&kf_s[u * 64 + fb + j];
            X_s[(fb + j + 0) * 64 + u] = w.x;
            X_s[(fb + j + 1) * 64 + u] = w.y;
            X_s[(fb + j + 2) * 64 + u] = w.z;
            X_s[(fb + j + 3) * 64 + u] = w.w;
        }
    }
    {
        int f = tid & 63, hlf = tid >> 6;
        float ps = 0.f;
        for (int u = hlf * 32; u < hlf * 32 + 32; u++) ps += kf_s[u * 64 + f];
        part_s[hlf * 64 + f] = ps;
    }
    __syncthreads();
    {
        u64 acc2[8][2] = {};
#pragma unroll
        for (int k = 0; k < 64; k += 4)
            micro84p<64, 64>(X_s, vp_s, 8 * rt, 4 * ct, k, acc2);
        float* pS_out = g_pS + ((size_t)bh * NCH + c) * 4096;
#pragma unroll
        for (int i = 0; i < 8; i++) {
            float2 p0 = upk(acc2[i][0]), p1 = upk(acc2[i][1]);
            *(float4*)&pS_out[(8 * rt + i) * 64 + 4 * ct] = make_float4(p0.x, p0.y, p1.x, p1.y);
        }
        if (tid < 64)
            g_pK[((size_t)bh * NCH + c) * 64 + tid] = part_s[tid] + part_s[64 + tid];
    }
    __threadfence();
    __syncthreads();
    if (tid == 0) atomicOr(&g_done[bh], 1u << c);

    // ---- P2: wait for all earlier chunks of this bh ----
    unsigned need = (1u << c) - 1u;
    if (tid == 0 && need) {
        while ((atomicOr(&g_done[bh], 0u) & need) != need) __nanosleep(64);
    }
    __syncthreads();

    // ---- P3: qt = qf / cumsum(kf) ----
    {
        int f = tid & 63, hlf = tid >> 6;
        float base = 0.f;
        for (int c2 = 0; c2 < c; c2++)
            base += g_pK[((size_t)bh * NCH + c2) * 64 + f];
        float kc = base + (hlf ? part_s[f] : 0.f);   // part_s still holds half-sums
        for (int u = hlf * 32; u < hlf * 32 + 32; u++) {
            kc += kf_s[u * 64 + f];
            qt_s[u * 64 + f] = __fdividef(qt_s[u * 64 + f], kc);
        }
    }
    __syncthreads();

    // ---- P4: preS rebuild (batched MLP loads) + inter-chunk GEMM ----
    u64 acc[8][2] = {};
    if (c > 0) {
        float4 a4[8];
#pragma unroll
        for (int j = 0; j < 8; j++) a4[j] = make_float4(0.f, 0.f, 0.f, 0.f);
        const float4* base4 = (const float4*)(g_pS + (size_t)bh * NCH * 4096);
        for (int c2 = 0; c2 < c; c2++) {
#pragma unroll
            for (int j = 0; j < 8; j++) {
                float4 t = base4[c2 * 1024 + j * 128 + tid];
                a4[j].x += t.x; a4[j].y += t.y; a4[j].z += t.z; a4[j].w += t.w;
            }
        }
#pragma unroll
        for (int j = 0; j < 8; j++) ((float4*)X_s)[j * 128 + tid] = a4[j];
        __syncthreads();
#pragma unroll
        for (int k = 0; k < 64; k += 4)
            micro84p<64, 64>(qt_s, X_s, 8 * rt, 4 * ct, k, acc);
    }
    __syncthreads();

    // ---- P5: intra-chunk (scores, mask, @vp) ----
    {   // rebuild kf^T in X_s
        int u = tid >> 1, fb = (tid & 1) * 32;
#pragma unroll
        for (int j = 0; j < 32; j += 4) {
            float4 w = *(const float4*)&kf_s[u * 64 + fb + j];
            X_s[(fb + j + 0) * 64 + u] = w.x;
            X_s[(fb + j + 1) * 64 + u] = w.y;
            X_s[(fb + j + 2) * 64 + u] = w.z;
            X_s[(fb + j + 3) * 64 + u] = w.w;
        }
    }
    __syncthreads();
    u64 acc1[8][2] = {};
#pragma unroll
    for (int k = 0; k < 64; k += 4)
        micro84p<64, 64>(qt_s, X_s, 8 * rt, 4 * ct, k, acc1);
    __syncthreads();
#pragma unroll
    for (int i = 0; i < 8; i++) {
        int r = 8 * rt + i;
        float2 p0 = upk(acc1[i][0]), p1 = upk(acc1[i][1]);
        float4 vv;
        vv.x = (4 * ct + 0 <= r) ? p0.x : 0.f;
        vv.y = (4 * ct + 1 <= r) ? p0.y : 0.f;
        vv.z = (4 * ct + 2 <= r) ? p1.x : 0.f;
        vv.w = (4 * ct + 3 <= r) ? p1.y : 0.f;
        *(float4*)&X_s[r * 64 + 4 * ct] = vv;
    }
    __syncthreads();
#pragma unroll
    for (int k = 0; k < 64; k += 4)
        micro84p<64, 64>(X_s, vp_s, 8 * rt, 4 * ct, k, acc);

#pragma unroll
    for (int i = 0; i < 8; i++) {
        int s = c * CHUNK + 8 * rt + i;
        float2 p0 = upk(acc[i][0]), p1 = upk(acc[i][1]);
        *(float4*)&g_attn[((size_t)b * SEQ + s) * DMODEL + h * DEP + 4 * ct] =
            make_float4(p0.x, p0.y, p1.x, p1.y);
    }
    // publish this head's attn rows for (b, c)
    __threadfence();
    __syncthreads();
    if (tid == 0) atomicAdd(&g_adone[b * NCH + c], 1u);

    // ---- P6: fused fc — output tile rows of (b,c), cols h*64..h*64+63, full K=512 ----
    if (tid == 0) {
        while (atomicAdd(&g_adone[b * NCH + c], 0u) < (unsigned)HEADS) __nanosleep(128);
        __threadfence();
    }
    __syncthreads();
    {
        int o0 = h * 64;
        int r0g = b * SEQ + c * CHUNK;
        u64 acc3[8][2];
        {
            u64 b0 = pk2b(bfc[o0 + 4 * ct + 0], bfc[o0 + 4 * ct + 1]);
            u64 b1 = pk2b(bfc[o0 + 4 * ct + 2], bfc[o0 + 4 * ct + 3]);
#pragma unroll
            for (int i = 0; i < 8; i++) { acc3[i][0] = b0; acc3[i][1] = b1; }
        }
        for (int kt = 0; kt < DMODEL; kt += 32) {
            // stage A 64x32 (attn rows) into X_s
            for (int i = tid; i < 512; i += 128) {
                int r = i >> 3, kk4 = (i & 7) * 4;
                float4 v = __ldcg((const float4*)&g_attn[(size_t)(r0g + r) * DMODEL + kt + kk4]);
                *(float4*)&X_s[r * 32 + kk4] = v;
            }
            // stage Bt 32x64 into w_s: w_s[e][o] = Wfc[o0+o][kt+e]
            for (int i = tid; i < 512; i += 128) {
                int o = i >> 3, e4 = (i & 7) * 4;
                float4 w = *(const float4*)&Wfc[(size_t)(o0 + o) * DMODEL + kt + e4];
                w_s[(e4 + 0) * 64 + o] = w.x;
                w_s[(e4 + 1) * 64 + o] = w.y;
                w_s[(e4 + 2) * 64 + o] = w.z;
                w_s[(e4 + 3) * 64 + o] = w.w;
            }
            __syncthreads();
#pragma unroll
            for (int k = 0; k < 32; k += 4)
                micro84p<32, 64>(X_s, w_s, 8 * rt, 4 * ct, k, acc3);
            __syncthreads();
        }
#pragma unroll
        for (int i = 0; i < 8; i++) {
            int r = r0g + 8 * rt + i;
            float2 p0 = upk(acc3[i][0]), p1 = upk(acc3[i][1]);
            *(float4*)&out[(size_t)r * DMODEL + o0 + 4 * ct] =
                make_float4(p0.x, p0.y, p1.x, p1.y);
        }
    }
}

// ---------------- launch ----------------
extern "C" void kernel_launch(void* const* d_in, const int* in_sizes, int n_in,
                              void* d_out, int out_size) {
    (void)in_sizes; (void)n_in; (void)out_size;
    const float* q    = (const float*)d_in[0];
    const float* k    = (const float*)d_in[1];
    const float* v    = (const float*)d_in[2];
    const float* Wq   = (const float*)d_in[3];
    const float* bq   = (const float*)d_in[4];
    const float* Wk   = (const float*)d_in[5];
    const float* bk   = (const float*)d_in[6];
    const float* Wv   = (const float*)d_in[7];
    const float* bv   = (const float*)d_in[8];
    const float* orfq = (const float*)d_in[9];
    const float* orfk = (const float*)d_in[10];
    const float* Wfc  = (const float*)d_in[11];
    const float* bfc  = (const float*)d_in[12];
    float* out = (float*)d_out;

    static bool attr_set = false;
    if (!attr_set) {
        cudaFuncSetAttribute(mega_kernel, cudaFuncAttributeMaxDynamicSharedMemorySize, 81920);
        attr_set = true;
    }

    prep_kernel<<<17, 256>>>(Wq, bq, Wk, bk, orfq, orfk, Wv);
    mega_kernel<<<dim3(BH, NCH), 128, 81920>>>(q, k, v, bv, Wfc, bfc, out);
}